// round 4
// baseline (speedup 1.0000x reference)
#include <cuda_runtime.h>
#include <math.h>

#define PI_F 3.14159265358979323846f

static const int B = 32, C = 4, H = 512, W = 512;
static const int SMEM_FLOATS = 12288;   // 48KB static shared window

__device__ __forceinline__ float clampf_(float v, float lo, float hi) {
    return fminf(fmaxf(v, lo), hi);
}

// ---------------------------------------------------------------------------
// Fused kernel with SMEM-staged bilinear sampling.
//  - per-thread recompute of fwd/inv affine matrices from fc2 (fp32)
//  - writes grid + inv_grid (float2); mat/inv_mat from one block
//  - per-block: compute source footprint window from the 4 tile-corner
//    preimages (uniform per block). If it fits in 48KB smem -> stage each
//    channel cooperatively, sample via LDS. Else -> direct-gather fallback.
// Warp tile: 8 wide x 4 tall; block tile 32x8.
// ---------------------------------------------------------------------------
__global__ __launch_bounds__(256)
void fused_affine_kernel(const float* __restrict__ src,
                         const float* __restrict__ fc2,
                         float* __restrict__ out_trans,
                         float* __restrict__ out_mat,
                         float* __restrict__ out_inv,
                         float* __restrict__ out_grid,
                         float* __restrict__ out_invgrid) {
    __shared__ float sm[SMEM_FLOATS];

    const int b = blockIdx.z;

    // --- rebuild matrices in registers (uniform across block) ---
    const float* __restrict__ f = fc2 + b * 7;
    float f0 = __ldg(&f[0]), f1 = __ldg(&f[1]), f2 = __ldg(&f[2]);
    float f3 = __ldg(&f[3]), f4 = __ldg(&f[4]), f5 = __ldg(&f[5]);
    float f6 = __ldg(&f[6]);

    const float theta = clampf_(f0 * 0.3f, -1.f, 1.f) * PI_F;
    const float sx = clampf_(f1 * 0.3f + 1.0f, 0.f, 5.f);
    const float sy = clampf_(f2 * 0.3f + 1.0f, 0.f, 5.f);
    const float tx = f3 * 0.3f;
    const float ty = f4 * 0.3f;
    const float shxy = clampf_(f5 * 0.3f, -1.f, 1.f) * PI_F;
    const float shyx = clampf_(f6 * 0.3f, -1.f, 1.f) * PI_F;

    const float c = cosf(theta), s = sinf(theta);
    const float a  = fmaf(shxy * sy, s, sx * c);
    const float bb = fmaf(shxy * sy, c, -sx * s);
    const float d  = fmaf(shyx * sx, c, sy * s);
    const float e  = fmaf(-shyx * sx, s, sy * c);

    const float det = fmaf(a, e, -bb * d);
    const float rdet = 1.0f / det;
    const float ia  = e * rdet;
    const float ib  = -bb * rdet;
    const float itx = fmaf(bb, ty, -e * tx) * rdet;
    const float id  = -d * rdet;
    const float ie  = a * rdet;
    const float ity = fmaf(d, tx, -a * ty) * rdet;

    if (blockIdx.x == 0 && blockIdx.y == 0 && threadIdx.x == 0) {
        float* om = out_mat + b * 9;
        om[0] = a;  om[1] = bb; om[2] = tx;
        om[3] = d;  om[4] = e;  om[5] = ty;
        om[6] = 0.f; om[7] = 0.f; om[8] = 1.f;
        float* oi = out_inv + b * 9;
        oi[0] = ia; oi[1] = ib; oi[2] = itx;
        oi[3] = id; oi[4] = ie; oi[5] = ity;
        oi[6] = 0.f; oi[7] = 0.f; oi[8] = 1.f;
    }

    // --- pixel coordinates: 8x4 warp tile, 32x8 block tile ---
    const int tid = threadIdx.x;
    const int lane = tid & 31;
    const int warp = tid >> 5;
    const int lx = lane & 7;
    const int ly = lane >> 3;
    const int wx = warp & 3;
    const int wy = warp >> 2;

    const int W0 = blockIdx.x * 32;
    const int H0 = blockIdx.y * 8;
    const int w = W0 + wx * 8 + lx;
    const int h = H0 + wy * 4 + ly;
    const int pix = h * W + w;

    const float x = (2.0f * (float)w + 1.0f) * (1.0f / (float)W) - 1.0f;
    const float y = (2.0f * (float)h + 1.0f) * (1.0f / (float)H) - 1.0f;

    const float gx = fmaf(a, x, fmaf(bb, y, tx));
    const float gy = fmaf(d, x, fmaf(e, y, ty));
    const float igx = fmaf(ia, x, fmaf(ib, y, itx));
    const float igy = fmaf(id, x, fmaf(ie, y, ity));

    const size_t gidx = (size_t)b * (H * W) + (size_t)pix;
    reinterpret_cast<float2*>(out_grid)[gidx]    = make_float2(gx, gy);
    reinterpret_cast<float2*>(out_invgrid)[gidx] = make_float2(igx, igy);

    // --- bilinear taps ---
    const float ixf = ((gx + 1.0f) * (float)W - 1.0f) * 0.5f;
    const float iyf = ((gy + 1.0f) * (float)H - 1.0f) * 0.5f;
    const float x0f = floorf(ixf);
    const float y0f = floorf(iyf);
    const float wxf = ixf - x0f;
    const float wyf = iyf - y0f;
    const int x0 = (int)x0f;
    const int y0 = (int)y0f;
    const int x1 = x0 + 1;
    const int y1 = y0 + 1;

    const float vx0 = (x0 >= 0 && x0 < W) ? 1.0f : 0.0f;
    const float vx1 = (x1 >= 0 && x1 < W) ? 1.0f : 0.0f;
    const float vy0 = (y0 >= 0 && y0 < H) ? 1.0f : 0.0f;
    const float vy1 = (y1 >= 0 && y1 < H) ? 1.0f : 0.0f;

    const int cx0 = min(max(x0, 0), W - 1);
    const int cx1 = min(max(x1, 0), W - 1);
    const int cy0 = min(max(y0, 0), H - 1);
    const int cy1 = min(max(y1, 0), H - 1);

    const float w00 = (1.0f - wxf) * (1.0f - wyf) * vx0 * vy0;
    const float w01 = wxf * (1.0f - wyf) * vx1 * vy0;
    const float w10 = (1.0f - wxf) * wyf * vx0 * vy1;
    const float w11 = wxf * wyf * vx1 * vy1;

    const float* __restrict__ sb = src + (size_t)b * C * H * W;
    float* __restrict__ ob = out_trans + (size_t)b * C * H * W;

    // --- block source window from 4 corner preimages (uniform per block) ---
    const float xA = (2.0f * (float)W0 + 1.0f) * (1.0f / (float)W) - 1.0f;
    const float xBc = (2.0f * (float)(W0 + 31) + 1.0f) * (1.0f / (float)W) - 1.0f;
    const float yA = (2.0f * (float)H0 + 1.0f) * (1.0f / (float)H) - 1.0f;
    const float yBc = (2.0f * (float)(H0 + 7) + 1.0f) * (1.0f / (float)H) - 1.0f;

    // source-pixel coords of corners
    #define SRC_PX(X, Y) ((fmaf(a, (X), fmaf(bb, (Y), tx)) + 1.0f) * (float)W - 1.0f) * 0.5f
    #define SRC_PY(X, Y) ((fmaf(d, (X), fmaf(e, (Y), ty)) + 1.0f) * (float)H - 1.0f) * 0.5f
    const float px00 = SRC_PX(xA, yA),  py00 = SRC_PY(xA, yA);
    const float px10 = SRC_PX(xBc, yA), py10 = SRC_PY(xBc, yA);
    const float px01 = SRC_PX(xA, yBc), py01 = SRC_PY(xA, yBc);
    const float px11 = SRC_PX(xBc, yBc), py11 = SRC_PY(xBc, yBc);
    #undef SRC_PX
    #undef SRC_PY

    const float pxmin = fminf(fminf(px00, px10), fminf(px01, px11));
    const float pxmax = fmaxf(fmaxf(px00, px10), fmaxf(px01, px11));
    const float pymin = fminf(fminf(py00, py10), fminf(py01, py11));
    const float pymax = fmaxf(fmaxf(py00, py10), fmaxf(py01, py11));

    const int xmin = min(max((int)floorf(pxmin), 0), W - 1);
    const int xmax = min(max((int)floorf(pxmax) + 1, 0), W - 1);
    const int ymin = min(max((int)floorf(pymin), 0), H - 1);
    const int ymax = min(max((int)floorf(pymax) + 1, 0), H - 1);

    const int xs = xmax - xmin + 1;
    const int ys = ymax - ymin + 1;
    const int pitch = xs | 1;                  // odd pitch -> spread LDS banks

    if ((long)ys * pitch <= SMEM_FLOATS) {
        // ---------------- SMEM-staged path ----------------
        const int ox0 = cx0 - xmin;
        const int ox1 = cx1 - xmin;
        const int oy0 = (cy0 - ymin) * pitch;
        const int oy1 = (cy1 - ymin) * pitch;

#pragma unroll
        for (int ch = 0; ch < C; ch++) {
            const float* __restrict__ img = sb + (size_t)ch * (H * W);
            // cooperative staging: 8 warps stride rows, lanes stride cols
            for (int r = warp; r < ys; r += 8) {
                const float* __restrict__ srow = img + (ymin + r) * W + xmin;
                float* __restrict__ drow = sm + r * pitch;
                for (int xx = lane; xx < xs; xx += 32)
                    drow[xx] = __ldg(&srow[xx]);
            }
            __syncthreads();

            const float v00 = sm[oy0 + ox0];
            const float v01 = sm[oy0 + ox1];
            const float v10 = sm[oy1 + ox0];
            const float v11 = sm[oy1 + ox1];
            const float r = fmaf(v00, w00, fmaf(v01, w01, fmaf(v10, w10, v11 * w11)));
            ob[(size_t)ch * (H * W) + pix] = r;
            __syncthreads();
        }
    } else {
        // ---------------- direct-gather fallback ----------------
        const int off00 = cy0 * W + cx0;
        const int off01 = cy0 * W + cx1;
        const int off10 = cy1 * W + cx0;
        const int off11 = cy1 * W + cx1;

#pragma unroll
        for (int ch = 0; ch < C; ch++) {
            const float* __restrict__ img = sb + (size_t)ch * (H * W);
            float v00 = __ldg(&img[off00]);
            float v01 = __ldg(&img[off01]);
            float v10 = __ldg(&img[off10]);
            float v11 = __ldg(&img[off11]);
            float r = fmaf(v00, w00, fmaf(v01, w01, fmaf(v10, w10, v11 * w11)));
            ob[(size_t)ch * (H * W) + pix] = r;
        }
    }
}

extern "C" void kernel_launch(void* const* d_in, const int* in_sizes, int n_in,
                              void* d_out, int out_size) {
    const float* src = (const float*)d_in[0];
    const float* fc2 = (const float*)d_in[1];
    float* out = (float*)d_out;

    // output layout: transformed | mat | inv_mat | grid | inv_grid
    const size_t n_trans = (size_t)B * C * H * W;          // 33,554,432
    const size_t n_mat = (size_t)B * 9;                    // 288
    const size_t n_grid = (size_t)B * H * W * 2;           // 16,777,216

    float* out_trans = out;
    float* out_mat   = out + n_trans;
    float* out_inv   = out_mat + n_mat;
    float* out_grid  = out_inv + n_mat;
    float* out_igrid = out_grid + n_grid;

    dim3 grid(W / 32, H / 8, B);
    fused_affine_kernel<<<grid, 256>>>(src, fc2, out_trans, out_mat, out_inv,
                                       out_grid, out_igrid);
}

// round 5
// speedup vs baseline: 2.3917x; 2.3917x over previous
#include <cuda_runtime.h>
#include <math.h>

#define PI_F 3.14159265358979323846f

static const int B = 32, C = 4, H = 512, W = 512;

__device__ __forceinline__ float clampf_(float v, float lo, float hi) {
    return fminf(fmaxf(v, lo), hi);
}

// ---------------------------------------------------------------------------
// Fused kernel (R3 structure) with float4 row-strip gathers:
//  - per-thread recompute of fwd/inv affine matrices from fc2 (fp32)
//  - writes grid + inv_grid (float2 streaming stores); mat/inv_mat once
//  - bilinear sample: per pixel-row, one aligned float4 strip covers both
//    x-taps in 75% of lanes; predicated scalar load covers the crossing case.
// Warp tile: 8 wide x 4 tall; block tile 32x8.
// ---------------------------------------------------------------------------
__global__ __launch_bounds__(256)
void fused_affine_kernel(const float* __restrict__ src,
                         const float* __restrict__ fc2,
                         float* __restrict__ out_trans,
                         float* __restrict__ out_mat,
                         float* __restrict__ out_inv,
                         float* __restrict__ out_grid,
                         float* __restrict__ out_invgrid) {
    const int b = blockIdx.z;

    // --- rebuild matrices in registers (uniform across block) ---
    const float* __restrict__ f = fc2 + b * 7;
    float f0 = __ldg(&f[0]), f1 = __ldg(&f[1]), f2 = __ldg(&f[2]);
    float f3 = __ldg(&f[3]), f4 = __ldg(&f[4]), f5 = __ldg(&f[5]);
    float f6 = __ldg(&f[6]);

    const float theta = clampf_(f0 * 0.3f, -1.f, 1.f) * PI_F;
    const float sx = clampf_(f1 * 0.3f + 1.0f, 0.f, 5.f);
    const float sy = clampf_(f2 * 0.3f + 1.0f, 0.f, 5.f);
    const float tx = f3 * 0.3f;
    const float ty = f4 * 0.3f;
    const float shxy = clampf_(f5 * 0.3f, -1.f, 1.f) * PI_F;
    const float shyx = clampf_(f6 * 0.3f, -1.f, 1.f) * PI_F;

    const float c = cosf(theta), s = sinf(theta);
    const float a  = fmaf(shxy * sy, s, sx * c);
    const float bb = fmaf(shxy * sy, c, -sx * s);
    const float d  = fmaf(shyx * sx, c, sy * s);
    const float e  = fmaf(-shyx * sx, s, sy * c);

    const float det = fmaf(a, e, -bb * d);
    const float rdet = 1.0f / det;
    const float ia  = e * rdet;
    const float ib  = -bb * rdet;
    const float itx = fmaf(bb, ty, -e * tx) * rdet;
    const float id  = -d * rdet;
    const float ie  = a * rdet;
    const float ity = fmaf(d, tx, -a * ty) * rdet;

    if (blockIdx.x == 0 && blockIdx.y == 0 && threadIdx.x == 0) {
        float* om = out_mat + b * 9;
        om[0] = a;  om[1] = bb; om[2] = tx;
        om[3] = d;  om[4] = e;  om[5] = ty;
        om[6] = 0.f; om[7] = 0.f; om[8] = 1.f;
        float* oi = out_inv + b * 9;
        oi[0] = ia; oi[1] = ib; oi[2] = itx;
        oi[3] = id; oi[4] = ie; oi[5] = ity;
        oi[6] = 0.f; oi[7] = 0.f; oi[8] = 1.f;
    }

    // --- pixel coordinates: 8x4 warp tile, 32x8 block tile ---
    const int tid = threadIdx.x;
    const int lane = tid & 31;
    const int warp = tid >> 5;
    const int lx = lane & 7;
    const int ly = lane >> 3;
    const int wx = warp & 3;
    const int wy = warp >> 2;

    const int w = blockIdx.x * 32 + wx * 8 + lx;
    const int h = blockIdx.y * 8 + wy * 4 + ly;
    const int pix = h * W + w;

    const float x = (2.0f * (float)w + 1.0f) * (1.0f / (float)W) - 1.0f;
    const float y = (2.0f * (float)h + 1.0f) * (1.0f / (float)H) - 1.0f;

    const float gx = fmaf(a, x, fmaf(bb, y, tx));
    const float gy = fmaf(d, x, fmaf(e, y, ty));
    const float igx = fmaf(ia, x, fmaf(ib, y, itx));
    const float igy = fmaf(id, x, fmaf(ie, y, ity));

    const size_t gidx = (size_t)b * (H * W) + (size_t)pix;
    __stcs(reinterpret_cast<float2*>(out_grid) + gidx,    make_float2(gx, gy));
    __stcs(reinterpret_cast<float2*>(out_invgrid) + gidx, make_float2(igx, igy));

    // --- bilinear taps ---
    const float ixf = ((gx + 1.0f) * (float)W - 1.0f) * 0.5f;
    const float iyf = ((gy + 1.0f) * (float)H - 1.0f) * 0.5f;
    const float x0f = floorf(ixf);
    const float y0f = floorf(iyf);
    const float wxf = ixf - x0f;
    const float wyf = iyf - y0f;
    const int x0 = (int)x0f;
    const int y0 = (int)y0f;
    const int x1 = x0 + 1;
    const int y1 = y0 + 1;

    const float vx0 = (x0 >= 0 && x0 < W) ? 1.0f : 0.0f;
    const float vx1 = (x1 >= 0 && x1 < W) ? 1.0f : 0.0f;
    const float vy0 = (y0 >= 0 && y0 < H) ? 1.0f : 0.0f;
    const float vy1 = (y1 >= 0 && y1 < H) ? 1.0f : 0.0f;

    const int cx0 = min(max(x0, 0), W - 1);
    const int cx1 = min(max(x1, 0), W - 1);
    const int cy0 = min(max(y0, 0), H - 1);
    const int cy1 = min(max(y1, 0), H - 1);

    const float w00 = (1.0f - wxf) * (1.0f - wyf) * vx0 * vy0;
    const float w01 = wxf * (1.0f - wyf) * vx1 * vy0;
    const float w10 = (1.0f - wxf) * wyf * vx0 * vy1;
    const float w11 = wxf * wyf * vx1 * vy1;

    // strip base / selection predicates (shared by both rows and all channels)
    const int q0 = cx0 & ~3;          // 16B-aligned strip base, always in-row
    const int r0 = cx0 - q0;          // 0..3
    const int i1 = cx1 - q0;          // r0 or r0+1, in [0..4]
    const bool need2 = (i1 == 4);     // right tap crosses into next strip
    const bool p00 = (r0 == 0), p01 = (r0 == 1), p02 = (r0 == 2);
    // for v01 via strip (i1 in 0..3): value = A[i1]
    const bool q00 = (i1 == 0), q01 = (i1 == 1), q02 = (i1 == 2);

    const int row0 = cy0 * W;
    const int row1 = cy1 * W;

    const float* __restrict__ sb = src + (size_t)b * C * H * W;
    float* __restrict__ ob = out_trans + (size_t)b * C * H * W;

#pragma unroll
    for (int ch = 0; ch < C; ch++) {
        const float* __restrict__ img = sb + (size_t)ch * (H * W);

        const float4 A0 = __ldg(reinterpret_cast<const float4*>(img + row0 + q0));
        const float4 A1 = __ldg(reinterpret_cast<const float4*>(img + row1 + q0));
        float e0 = 0.f, e1 = 0.f;
        if (need2) {
            e0 = __ldg(&img[row0 + cx1]);   // cx1 == q0 + 4, in-bounds
            e1 = __ldg(&img[row1 + cx1]);
        }

        const float v00 = p00 ? A0.x : (p01 ? A0.y : (p02 ? A0.z : A0.w));
        const float v10 = p00 ? A1.x : (p01 ? A1.y : (p02 ? A1.z : A1.w));
        const float s01 = q00 ? A0.x : (q01 ? A0.y : (q02 ? A0.z : A0.w));
        const float s11 = q00 ? A1.x : (q01 ? A1.y : (q02 ? A1.z : A1.w));
        const float v01 = need2 ? e0 : s01;
        const float v11 = need2 ? e1 : s11;

        const float r = fmaf(v00, w00, fmaf(v01, w01, fmaf(v10, w10, v11 * w11)));
        __stcs(&ob[(size_t)ch * (H * W) + pix], r);
    }
}

extern "C" void kernel_launch(void* const* d_in, const int* in_sizes, int n_in,
                              void* d_out, int out_size) {
    const float* src = (const float*)d_in[0];
    const float* fc2 = (const float*)d_in[1];
    float* out = (float*)d_out;

    // output layout: transformed | mat | inv_mat | grid | inv_grid
    const size_t n_trans = (size_t)B * C * H * W;          // 33,554,432
    const size_t n_mat = (size_t)B * 9;                    // 288
    const size_t n_grid = (size_t)B * H * W * 2;           // 16,777,216

    float* out_trans = out;
    float* out_mat   = out + n_trans;
    float* out_inv   = out_mat + n_mat;
    float* out_grid  = out_inv + n_mat;
    float* out_igrid = out_grid + n_grid;

    dim3 grid(W / 32, H / 8, B);
    fused_affine_kernel<<<grid, 256>>>(src, fc2, out_trans, out_mat, out_inv,
                                       out_grid, out_igrid);
}